// round 14
// baseline (speedup 1.0000x reference)
#include <cuda_runtime.h>
#include <math.h>

// ---------------------------------------------------------------------------
// PositionEvaluator, round 13: column-pair packing (round-12 design, compile
// fix: template<int CIN> gated_stage replaces the lambda/tag hack).
// Envelope: NT=256, R=16 rows/CTA, occ=1, grid=6250 (the config that benches).
// Activations stored as u64 = (col c, col c+1) for ONE row: thread =
// (row r = tid&15, group g = tid>>4), J=8 outputs.
//  - weights load as ulonglong2 (two packed cols differ per lane) -> NO dup MOVs
//  - xv LDS amortized over J=8 outputs (halved vs J=4)
//  - R9's ping-pong weight prefetch retained (covers ~250cyc L2 latency)
// Even/odd column partial sums live in the u64 accumulator; epilogue adds
// lo+hi -> scalar, stores 32-bit into the packed layout.
// ---------------------------------------------------------------------------

#define R  16
#define NT 256

typedef unsigned long long u64;
union F2 { u64 u; float2 f; };

__device__ __forceinline__ u64 ffma2(u64 a, u64 b, u64 c) {
  u64 d; asm("fma.rn.f32x2 %0, %1, %2, %3;" : "=l"(d) : "l"(a), "l"(b), "l"(c)); return d;
}
__device__ __forceinline__ float lohi(u64 v) { F2 t; t.u = v; return t.f.x + t.f.y; }

struct SM {
  u64 sv[3][128][R];   // vector activations: [comp][colpair][row]
  u64 sh[3][128][R];   // vh / d scratch
  u64 sn[128][R];      // norms, col-paired
  u64 ss[128][R];      // scalar activations, col-paired (256 ch)
  u64 so[64][R];       // out_s (128 ch) / final reduce scratch
  float rp[3][R];
  int  nidx[R];
};

// ---------------- vector dot: J=8 outputs, ping-pong ull2 weights ----------
// acc over col-pairs; output channel o = oBase + g + 16*j.
template<int CIN, bool NORM, bool GATED>
__device__ __forceinline__ void vdotH(const float* __restrict__ W, int oBase,
                                      u64 (*x)[128][R],
                                      u64 (*y)[128][R],
                                      u64 (*nrm)[R],
                                      const float* gate,
                                      int g, int r)
{
  constexpr int J = 8;
  constexpr int NCH = CIN / 4;           // ull2 chunks (4 cols each)
  static_assert(NCH % 2 == 0, "NCH even");
  const ulonglong2* rowp[J];
#pragma unroll
  for (int j = 0; j < J; ++j)
    rowp[j] = reinterpret_cast<const ulonglong2*>(W + (size_t)(oBase + g + 16 * j) * CIN);

  u64 acc[J][3];
#pragma unroll
  for (int j = 0; j < J; ++j) { acc[j][0] = 0ull; acc[j][1] = 0ull; acc[j][2] = 0ull; }

  ulonglong2 A[J], B[J];
#pragma unroll
  for (int j = 0; j < J; ++j) A[j] = __ldg(rowp[j]);

#pragma unroll 1
  for (int ch = 0; ch < NCH; ch += 2) {
#pragma unroll
    for (int j = 0; j < J; ++j) B[j] = __ldg(rowp[j] + ch + 1);
    {
      u64 xv[3][2];
#pragma unroll
      for (int i = 0; i < 3; ++i) {
        xv[i][0] = x[i][2 * ch][r];
        xv[i][1] = x[i][2 * ch + 1][r];
      }
#pragma unroll
      for (int j = 0; j < J; ++j)
#pragma unroll
        for (int i = 0; i < 3; ++i) {
          acc[j][i] = ffma2(A[j].x, xv[i][0], acc[j][i]);
          acc[j][i] = ffma2(A[j].y, xv[i][1], acc[j][i]);
        }
    }
    const int cn = (ch + 2 < NCH) ? (ch + 2) : 0;
#pragma unroll
    for (int j = 0; j < J; ++j) A[j] = __ldg(rowp[j] + cn);
    {
      u64 xv[3][2];
#pragma unroll
      for (int i = 0; i < 3; ++i) {
        xv[i][0] = x[i][2 * ch + 2][r];
        xv[i][1] = x[i][2 * ch + 3][r];
      }
#pragma unroll
      for (int j = 0; j < J; ++j)
#pragma unroll
        for (int i = 0; i < 3; ++i) {
          acc[j][i] = ffma2(B[j].x, xv[i][0], acc[j][i]);
          acc[j][i] = ffma2(B[j].y, xv[i][1], acc[j][i]);
        }
    }
  }

  const int par = g & 1;
#pragma unroll
  for (int j = 0; j < J; ++j) {
    const int o = oBase + g + 16 * j;
    const int cpo = o >> 1;
    float s0 = lohi(acc[j][0]);
    float s1 = lohi(acc[j][1]);
    float s2 = lohi(acc[j][2]);
    if (GATED) { const float gt = gate[j]; s0 *= gt; s1 *= gt; s2 *= gt; }
    reinterpret_cast<float*>(&y[0][cpo][r])[par] = s0;
    reinterpret_cast<float*>(&y[1][cpo][r])[par] = s1;
    reinterpret_cast<float*>(&y[2][cpo][r])[par] = s2;
    if (NORM)
      reinterpret_cast<float*>(&nrm[cpo][r])[par] = sqrtf(s0 * s0 + s1 * s1 + s2 * s2);
  }
}

// ---------------- scalar dot segment, J=8, ping-pong ----------------------
template<int K, int OFF, int Kseg>
__device__ __forceinline__ void sdotH(const float* __restrict__ W, int oBase,
                                      u64 (*x)[R],
                                      u64 (&acc)[8], int g, int r)
{
  constexpr int J = 8;
  constexpr int NCH = Kseg / 4;
  static_assert(NCH % 2 == 0, "NCH even");
  const ulonglong2* rowp[J];
#pragma unroll
  for (int j = 0; j < J; ++j)
    rowp[j] = reinterpret_cast<const ulonglong2*>(W + (size_t)(oBase + g + 16 * j) * K + OFF);

  ulonglong2 A[J], B[J];
#pragma unroll
  for (int j = 0; j < J; ++j) A[j] = __ldg(rowp[j]);

#pragma unroll 1
  for (int ch = 0; ch < NCH; ch += 2) {
#pragma unroll
    for (int j = 0; j < J; ++j) B[j] = __ldg(rowp[j] + ch + 1);
    {
      const u64 x0 = x[2 * ch][r];
      const u64 x1 = x[2 * ch + 1][r];
#pragma unroll
      for (int j = 0; j < J; ++j) {
        acc[j] = ffma2(A[j].x, x0, acc[j]);
        acc[j] = ffma2(A[j].y, x1, acc[j]);
      }
    }
    const int cn = (ch + 2 < NCH) ? (ch + 2) : 0;
#pragma unroll
    for (int j = 0; j < J; ++j) A[j] = __ldg(rowp[j] + cn);
    {
      const u64 x0 = x[2 * ch + 2][r];
      const u64 x1 = x[2 * ch + 3][r];
#pragma unroll
      for (int j = 0; j < J; ++j) {
        acc[j] = ffma2(B[j].x, x0, acc[j]);
        acc[j] = ffma2(B[j].y, x1, acc[j]);
      }
    }
  }
}

// ---------------- gated vector-output stage (gate from so, vh in sh) -------
template<int CIN>
__device__ __forceinline__ void gated_stage(SM& S, const float* __restrict__ Wvo,
                                            const float* __restrict__ Wg,
                                            const float* __restrict__ bg,
                                            int oBase, int g, int r)
{
  u64 gacc[8];
#pragma unroll
  for (int j = 0; j < 8; ++j) gacc[j] = 0ull;
  sdotH<128, 0, 128>(Wg, oBase, S.so, gacc, g, r);
  float gate[8];
#pragma unroll
  for (int j = 0; j < 8; ++j) {
    const float b = __ldg(&bg[oBase + g + 16 * j]);
    gate[j] = 1.f / (1.f + __expf(-(lohi(gacc[j]) + b)));
  }
  vdotH<CIN, false, true>(Wvo, oBase, S.sh, S.sv, S.sn, gate, g, r);
}

// ---------------- vn_leaky_relu over NCH8*16 channels ----------------------
template<int NJ>
__device__ __forceinline__ void vnleaky(SM& S, int g, int r, int par)
{
#pragma unroll
  for (int j = 0; j < NJ; ++j) {
    const int o = g + 16 * j, cpo = o >> 1;
    float x0 = reinterpret_cast<float*>(&S.sv[0][cpo][r])[par];
    float x1 = reinterpret_cast<float*>(&S.sv[1][cpo][r])[par];
    float x2 = reinterpret_cast<float*>(&S.sv[2][cpo][r])[par];
    float d0 = reinterpret_cast<float*>(&S.sh[0][cpo][r])[par];
    float d1 = reinterpret_cast<float*>(&S.sh[1][cpo][r])[par];
    float d2 = reinterpret_cast<float*>(&S.sh[2][cpo][r])[par];
    const float dot = x0 * d0 + x1 * d1 + x2 * d2;
    const float dsq = d0 * d0 + d1 * d1 + d2 * d2;
    const float t = dot / (dsq + 1e-6f);
    const bool pos = (dot >= 0.f);
    const float n0 = pos ? x0 : (x0 - t * d0);
    const float n1 = pos ? x1 : (x1 - t * d1);
    const float n2 = pos ? x2 : (x2 - t * d2);
    reinterpret_cast<float*>(&S.sv[0][cpo][r])[par] = 0.2f * x0 + 0.8f * n0;
    reinterpret_cast<float*>(&S.sv[1][cpo][r])[par] = 0.2f * x1 + 0.8f * n1;
    reinterpret_cast<float*>(&S.sv[2][cpo][r])[par] = 0.2f * x2 + 0.8f * n2;
  }
}

__global__ __launch_bounds__(NT, 1)
void pe_kernel(const float* __restrict__ h_sca, const float* __restrict__ h_vec,
               const float* __restrict__ pos_compose, const float* __restrict__ pos,
               const float* __restrict__ g1_Wvh, const float* __restrict__ g1_Ws,
               const float* __restrict__ g1_Wvo, const float* __restrict__ g1_Wg,
               const float* __restrict__ g1_bg,  const float* __restrict__ g1_Wd,
               const float* __restrict__ g2_Wvh, const float* __restrict__ g2_Ws,
               const float* __restrict__ g2_Wvo, const float* __restrict__ g2_Wg,
               const float* __restrict__ g2_bg,
               const float* __restrict__ a1_Wvh, const float* __restrict__ a1_Ws,
               const float* __restrict__ a1_Wvo, const float* __restrict__ a1_Wg,
               const float* __restrict__ a1_bg,  const float* __restrict__ a1_Wd,
               const float* __restrict__ a2_Wvh, const float* __restrict__ a2_Ws,
               const float* __restrict__ a2_Wvo, const float* __restrict__ a2_Wg,
               const float* __restrict__ a2_bg,  const float* __restrict__ a2_Wd,
               const float* __restrict__ f_Wvh,  const float* __restrict__ f_Ws,
               const int* __restrict__ idx_focal,
               float* __restrict__ out, int F)
{
  extern __shared__ char smraw[];
  SM& S = *reinterpret_cast<SM*>(smraw);
  const int tid = threadIdx.x;
  const int r = tid & 15;     // row 0..15
  const int g = tid >> 4;     // group 0..15
  const int par = g & 1;
  const int row0 = blockIdx.x * R;

  if (tid < R) {
    const int row = row0 + tid;
    S.nidx[tid] = (row < F) ? idx_focal[row] : 0;
  }
  __syncthreads();

  if (tid < 3 * R) {
    const int rr = tid / 3, i = tid % 3;
    const int row = row0 + rr;
    const int n = S.nidx[rr];
    const float pv = (row < F) ? pos[(size_t)row * 3 + i] : 0.f;
    S.rp[i][rr] = pv - pos_compose[(size_t)n * 3 + i];
  }

  // gather into packed layout: thread tid handles channel c=tid
  for (int rr = 0; rr < R; ++rr) {
    const size_t n = (size_t)S.nidx[rr];
    reinterpret_cast<float*>(&S.ss[tid >> 1][rr])[tid & 1] = __ldg(&h_sca[n * 256 + tid]);
    if (tid < 192) {
      const int comp = tid % 3, c = tid / 3;
      reinterpret_cast<float*>(&S.sv[comp][c >> 1][rr])[c & 1] = __ldg(&h_vec[n * 192 + tid]);
    }
  }
  __syncthreads();

  // ================= g1: gv_perceptron =================
  vdotH<64, true, false>(g1_Wvh, 0, S.sv, S.sh, S.sn, nullptr, g, r);
  __syncthreads();
  { u64 acc[8];
#pragma unroll
    for (int j = 0; j < 8; ++j) acc[j] = 0ull;
    sdotH<384, 0, 128>(g1_Ws, 0, S.sn, acc, g, r);
    sdotH<384, 128, 256>(g1_Ws, 0, S.ss, acc, g, r);
#pragma unroll
    for (int j = 0; j < 8; ++j) {
      const int o = g + 16 * j;
      reinterpret_cast<float*>(&S.so[o >> 1][r])[par] = lohi(acc[j]);
    } }
  __syncthreads();
  gated_stage<128>(S, g1_Wvo, g1_Wg, g1_bg, 0, g, r);
#pragma unroll
  for (int j = 0; j < 8; ++j) {
    const int o = g + 16 * j;
    float v = reinterpret_cast<float*>(&S.so[o >> 1][r])[par];
    v = v >= 0.f ? v : 0.01f * v;
    reinterpret_cast<float*>(&S.ss[o >> 1][r])[par] = v;
  }
  __syncthreads();
  vdotH<128, false, false>(g1_Wd, 0, S.sv, S.sh, S.sn, nullptr, g, r);
  __syncthreads();
  vnleaky<8>(S, g, r, par);
  __syncthreads();

  // ================= g2: gv_linear =================
  vdotH<128, true, false>(g2_Wvh, 0, S.sv, S.sh, S.sn, nullptr, g, r);
  __syncthreads();
  { u64 acc[8];
#pragma unroll
    for (int j = 0; j < 8; ++j) acc[j] = 0ull;
    sdotH<256, 0, 128>(g2_Ws, 0, S.sn, acc, g, r);
    sdotH<256, 128, 128>(g2_Ws, 0, S.ss, acc, g, r);
#pragma unroll
    for (int j = 0; j < 8; ++j) {
      const int o = g + 16 * j;
      reinterpret_cast<float*>(&S.so[o >> 1][r])[par] = lohi(acc[j]);
    } }
  __syncthreads();
  gated_stage<128>(S, g2_Wvo, g2_Wg, g2_bg, 0, g, r);
#pragma unroll
  for (int j = 0; j < 8; ++j) {
    const int o = g + 16 * j;
    reinterpret_cast<float*>(&S.ss[o >> 1][r])[par] =
        reinterpret_cast<float*>(&S.so[o >> 1][r])[par];
  }
  __syncthreads();

  // ================= a1: gv_perceptron (OUT=256) =================
  vdotH<128, true, false>(a1_Wvh, 0,   S.sv, S.sh, S.sn, nullptr, g, r);
  vdotH<128, true, false>(a1_Wvh, 128, S.sv, S.sh, S.sn, nullptr, g, r);
  __syncthreads();
  { u64 acc[8];
#pragma unroll
    for (int j = 0; j < 8; ++j) acc[j] = 0ull;
    sdotH<384, 0, 256>(a1_Ws, 0, S.sn, acc, g, r);
    sdotH<384, 256, 128>(a1_Ws, 0, S.ss, acc, g, r);
#pragma unroll
    for (int j = 0; j < 8; ++j) {
      const int o = g + 16 * j;
      reinterpret_cast<float*>(&S.so[o >> 1][r])[par] = lohi(acc[j]);
    } }
  __syncthreads();
  gated_stage<256>(S, a1_Wvo, a1_Wg, a1_bg, 0,   g, r);
  gated_stage<256>(S, a1_Wvo, a1_Wg, a1_bg, 128, g, r);
#pragma unroll
  for (int j = 0; j < 8; ++j) {
    const int o = g + 16 * j;
    float v = reinterpret_cast<float*>(&S.so[o >> 1][r])[par];
    v = v >= 0.f ? v : 0.01f * v;
    reinterpret_cast<float*>(&S.ss[o >> 1][r])[par] = v;
  }
  __syncthreads();
  vdotH<256, false, false>(a1_Wd, 0,   S.sv, S.sh, S.sn, nullptr, g, r);
  vdotH<256, false, false>(a1_Wd, 128, S.sv, S.sh, S.sn, nullptr, g, r);
  __syncthreads();
  vnleaky<16>(S, g, r, par);
  __syncthreads();

  // ===== split: inner = <x_vec2 (sv ch 128..255), relpos> -> ss ch 128..255
  {
    const float rp0 = S.rp[0][r], rp1 = S.rp[1][r], rp2 = S.rp[2][r];
#pragma unroll
    for (int j = 0; j < 8; ++j) {
      const int o2 = g + 16 * j;
      const int cp = 64 + (o2 >> 1);
      const float v0 = reinterpret_cast<float*>(&S.sv[0][cp][r])[par];
      const float v1 = reinterpret_cast<float*>(&S.sv[1][cp][r])[par];
      const float v2 = reinterpret_cast<float*>(&S.sv[2][cp][r])[par];
      reinterpret_cast<float*>(&S.ss[cp][r])[par] = v0 * rp0 + v1 * rp1 + v2 * rp2;
    }
  }
  __syncthreads();

  // ================= a2: gv_perceptron (on x_vec = sv ch 0..127) ==========
  vdotH<128, true, false>(a2_Wvh, 0, S.sv, S.sh, S.sn, nullptr, g, r);
  __syncthreads();
  { u64 acc[8];
#pragma unroll
    for (int j = 0; j < 8; ++j) acc[j] = 0ull;
    sdotH<384, 0, 128>(a2_Ws, 0, S.sn, acc, g, r);
    sdotH<384, 128, 256>(a2_Ws, 0, S.ss, acc, g, r);
#pragma unroll
    for (int j = 0; j < 8; ++j) {
      const int o = g + 16 * j;
      reinterpret_cast<float*>(&S.so[o >> 1][r])[par] = lohi(acc[j]);
    } }
  __syncthreads();
  gated_stage<128>(S, a2_Wvo, a2_Wg, a2_bg, 0, g, r);
#pragma unroll
  for (int j = 0; j < 8; ++j) {
    const int o = g + 16 * j;
    float v = reinterpret_cast<float*>(&S.so[o >> 1][r])[par];
    v = v >= 0.f ? v : 0.01f * v;
    reinterpret_cast<float*>(&S.ss[o >> 1][r])[par] = v;
  }
  __syncthreads();
  vdotH<128, false, false>(a2_Wd, 0, S.sv, S.sh, S.sn, nullptr, g, r);
  __syncthreads();
  vnleaky<8>(S, g, r, par);
  __syncthreads();

  // ================= final: out = [||f_Wvh@v|| (128), s3 (128)] @ f_Ws^T ===
  vdotH<128, true, false>(f_Wvh, 0, S.sv, S.sh, S.sn, nullptr, g, r);
  __syncthreads();
  {
    float acc = 0.f;
#pragma unroll
    for (int kk = 0; kk < 16; ++kk) {
      const int k = g * 16 + kk;
      float xv;
      if (k < 128) xv = reinterpret_cast<float*>(&S.sn[k >> 1][r])[k & 1];
      else         xv = reinterpret_cast<float*>(&S.ss[(k - 128) >> 1][r])[k & 1];
      acc = fmaf(__ldg(&f_Ws[k]), xv, acc);
    }
    reinterpret_cast<float*>(&S.so[g >> 1][r])[par] = acc;
  }
  __syncthreads();
  if (tid < R) {
    const int row = row0 + tid;
    float acc = 0.f;
#pragma unroll
    for (int gg = 0; gg < 16; ++gg)
      acc += reinterpret_cast<float*>(&S.so[gg >> 1][tid])[gg & 1];
    if (row < F) out[row] = acc;
  }
}

extern "C" void kernel_launch(void* const* d_in, const int* in_sizes, int n_in,
                              void* d_out, int out_size)
{
  const float* h_sca       = (const float*)d_in[0];
  const float* h_vec       = (const float*)d_in[1];
  const float* pos_compose = (const float*)d_in[2];
  const float* pos         = (const float*)d_in[3];
  const float* g1_Wvh = (const float*)d_in[4];
  const float* g1_Ws  = (const float*)d_in[5];
  const float* g1_Wvo = (const float*)d_in[6];
  const float* g1_Wg  = (const float*)d_in[7];
  const float* g1_bg  = (const float*)d_in[8];
  const float* g1_Wd  = (const float*)d_in[9];
  const float* g2_Wvh = (const float*)d_in[10];
  const float* g2_Ws  = (const float*)d_in[11];
  const float* g2_Wvo = (const float*)d_in[12];
  const float* g2_Wg  = (const float*)d_in[13];
  const float* g2_bg  = (const float*)d_in[14];
  const float* a1_Wvh = (const float*)d_in[15];
  const float* a1_Ws  = (const float*)d_in[16];
  const float* a1_Wvo = (const float*)d_in[17];
  const float* a1_Wg  = (const float*)d_in[18];
  const float* a1_bg  = (const float*)d_in[19];
  const float* a1_Wd  = (const float*)d_in[20];
  const float* a2_Wvh = (const float*)d_in[21];
  const float* a2_Ws  = (const float*)d_in[22];
  const float* a2_Wvo = (const float*)d_in[23];
  const float* a2_Wg  = (const float*)d_in[24];
  const float* a2_bg  = (const float*)d_in[25];
  const float* a2_Wd  = (const float*)d_in[26];
  const float* f_Wvh  = (const float*)d_in[27];
  const float* f_Ws   = (const float*)d_in[28];
  const int*   idx_focal = (const int*)d_in[29];

  const int F = in_sizes[3] / 3;   // pos is (F, 3)
  const int grid = (F + R - 1) / R;

  cudaFuncSetAttribute(pe_kernel, cudaFuncAttributeMaxDynamicSharedMemorySize,
                       (int)sizeof(SM));

  pe_kernel<<<grid, NT, sizeof(SM)>>>(
      h_sca, h_vec, pos_compose, pos,
      g1_Wvh, g1_Ws, g1_Wvo, g1_Wg, g1_bg, g1_Wd,
      g2_Wvh, g2_Ws, g2_Wvo, g2_Wg, g2_bg,
      a1_Wvh, a1_Ws, a1_Wvo, a1_Wg, a1_bg, a1_Wd,
      a2_Wvh, a2_Ws, a2_Wvo, a2_Wg, a2_bg, a2_Wd,
      f_Wvh, f_Ws, idx_focal,
      (float*)d_out, F);
}

// round 15
// speedup vs baseline: 1.1152x; 1.1152x over previous
#include <cuda_runtime.h>
#include <math.h>

// ---------------------------------------------------------------------------
// PositionEvaluator, round 14: R9 winning design (NT=256, R=16, occ=1,
// FFMA2 row pairs, J=4/Rt=2 balance) with DEEPER weight prefetch:
// 4-buffer ring, 4-column chunks, distance-2 -> ~2x the issue-time between a
// weight load and its use (>= the ~250cyc L2 latency), vs R9's distance-1
// which left ~60-150 cyc exposed per half-chunk.
// OUT=256 vector stages run as two J=4 passes to keep registers bounded.
// Thread map: p = tid & 7 (row pair 0..7), g = tid >> 3 (group 0..31).
// ---------------------------------------------------------------------------

#define R  16
#define G  32
#define NT 256

typedef unsigned long long u64;
union F2 { u64 u; float2 f; };

__device__ __forceinline__ u64 ffma2(u64 a, u64 b, u64 c) {
  u64 d; asm("fma.rn.f32x2 %0, %1, %2, %3;" : "=l"(d) : "l"(a), "l"(b), "l"(c)); return d;
}
__device__ __forceinline__ u64 fmul2(u64 a, u64 b) {
  u64 d; asm("mul.rn.f32x2 %0, %1, %2;" : "=l"(d) : "l"(a), "l"(b)); return d;
}
__device__ __forceinline__ u64 dup2(float w) {
  u64 d; asm("mov.b64 %0, {%1, %1};" : "=l"(d) : "f"(w)); return d;
}
__device__ __forceinline__ u64 ld2(const float* p) {
  return *reinterpret_cast<const u64*>(p);
}
__device__ __forceinline__ void st2(float* p, u64 v) {
  *reinterpret_cast<u64*>(p) = v;
}

struct SM {
  float sv[3][256][R];
  float sh[3][256][R];
  float snorm[256][R];
  float ssc[256][R];
  float so[128][R];
  float rp[3][R];
  int   nidx[R];
};

// ---- FMA over one 4-column chunk with given weight buffer (J=4) ----------
__device__ __forceinline__ void vfma_chunk(u64 (&acc)[4][3], const float4 (&Wb)[4],
                                           float (*x)[256][R], int cb, int p)
{
  u64 xv[3][4];
#pragma unroll
  for (int t = 0; t < 4; ++t) {
    xv[0][t] = ld2(&x[0][4 * cb + t][2 * p]);
    xv[1][t] = ld2(&x[1][4 * cb + t][2 * p]);
    xv[2][t] = ld2(&x[2][4 * cb + t][2 * p]);
  }
#pragma unroll
  for (int j = 0; j < 4; ++j) {
    const u64 w0 = dup2(Wb[j].x), w1 = dup2(Wb[j].y);
    const u64 w2 = dup2(Wb[j].z), w3 = dup2(Wb[j].w);
#pragma unroll
    for (int i = 0; i < 3; ++i) {
      acc[j][i] = ffma2(w0, xv[i][0], acc[j][i]);
      acc[j][i] = ffma2(w1, xv[i][1], acc[j][i]);
      acc[j][i] = ffma2(w2, xv[i][2], acc[j][i]);
      acc[j][i] = ffma2(w3, xv[i][3], acc[j][i]);
    }
  }
}

// ---- vector dot, J=4 outputs at o = oOff + g + G*j, distance-2 ring ------
template<int CIN>
__device__ __forceinline__ void vdot4(const float* __restrict__ W, int oOff,
                                      float (*x)[256][R],
                                      u64 (&acc)[4][3], int g, int p)
{
  constexpr int NCH = CIN / 4;          // 4-column chunks
  static_assert(NCH % 4 == 0, "NCH % 4");
  const float4* rowp[4];
#pragma unroll
  for (int j = 0; j < 4; ++j)
    rowp[j] = reinterpret_cast<const float4*>(W + (size_t)(oOff + g + G * j) * CIN);

  float4 W0[4], W1[4], W2[4], W3[4];
#pragma unroll
  for (int j = 0; j < 4; ++j) W0[j] = __ldg(rowp[j] + 0);
#pragma unroll
  for (int j = 0; j < 4; ++j) W1[j] = __ldg(rowp[j] + 1);

#pragma unroll 1
  for (int ch = 0; ch < NCH; ch += 4) {
    { const int ix = (ch + 2 < NCH) ? ch + 2 : 0;
#pragma unroll
      for (int j = 0; j < 4; ++j) W2[j] = __ldg(rowp[j] + ix); }
    vfma_chunk(acc, W0, x, ch, p);
    { const int ix = (ch + 3 < NCH) ? ch + 3 : 0;
#pragma unroll
      for (int j = 0; j < 4; ++j) W3[j] = __ldg(rowp[j] + ix); }
    vfma_chunk(acc, W1, x, ch + 1, p);
    { const int ix = (ch + 4 < NCH) ? ch + 4 : 0;
#pragma unroll
      for (int j = 0; j < 4; ++j) W0[j] = __ldg(rowp[j] + ix); }
    vfma_chunk(acc, W2, x, ch + 2, p);
    { const int ix = (ch + 5 < NCH) ? ch + 5 : 0;
#pragma unroll
      for (int j = 0; j < 4; ++j) W1[j] = __ldg(rowp[j] + ix); }
    vfma_chunk(acc, W3, x, ch + 3, p);
  }
}

// ---- scalar dot segment (R9 structure, J outputs, ping-pong) --------------
template<int J, int K, int OFF, int Kseg>
__device__ __forceinline__ void sdot_seg(const float* __restrict__ W,
                                         float (*x)[R],
                                         u64 (&acc)[J], int g, int p)
{
  constexpr int CH = (J >= 8) ? 8 : 16;
  constexpr int NF = CH / 4;
  static_assert(Kseg % (2 * CH) == 0, "Kseg mult");
  float4 A[J][NF], B[J][NF];
#pragma unroll
  for (int j = 0; j < J; ++j)
#pragma unroll
    for (int q = 0; q < NF; ++q)
      A[j][q] = __ldg(reinterpret_cast<const float4*>(W + (size_t)(g + G * j) * K + OFF) + q);
#pragma unroll 1
  for (int k = 0; k < Kseg; k += 2 * CH) {
#pragma unroll
    for (int j = 0; j < J; ++j)
#pragma unroll
      for (int q = 0; q < NF; ++q)
        B[j][q] = __ldg(reinterpret_cast<const float4*>(W + (size_t)(g + G * j) * K + OFF + k + CH) + q);
    {
      u64 xv[CH];
#pragma unroll
      for (int t = 0; t < CH; ++t) xv[t] = ld2(&x[k + t][2 * p]);
#pragma unroll
      for (int j = 0; j < J; ++j)
#pragma unroll
        for (int q = 0; q < NF; ++q) {
          acc[j] = ffma2(dup2(A[j][q].x), xv[4 * q + 0], acc[j]);
          acc[j] = ffma2(dup2(A[j][q].y), xv[4 * q + 1], acc[j]);
          acc[j] = ffma2(dup2(A[j][q].z), xv[4 * q + 2], acc[j]);
          acc[j] = ffma2(dup2(A[j][q].w), xv[4 * q + 3], acc[j]);
        }
    }
    const int kn = (k + 2 * CH < Kseg) ? (k + 2 * CH) : 0;
#pragma unroll
    for (int j = 0; j < J; ++j)
#pragma unroll
      for (int q = 0; q < NF; ++q)
        A[j][q] = __ldg(reinterpret_cast<const float4*>(W + (size_t)(g + G * j) * K + OFF + kn) + q);
    {
      u64 xv[CH];
#pragma unroll
      for (int t = 0; t < CH; ++t) xv[t] = ld2(&x[k + CH + t][2 * p]);
#pragma unroll
      for (int j = 0; j < J; ++j)
#pragma unroll
        for (int q = 0; q < NF; ++q) {
          acc[j] = ffma2(dup2(B[j][q].x), xv[4 * q + 0], acc[j]);
          acc[j] = ffma2(dup2(B[j][q].y), xv[4 * q + 1], acc[j]);
          acc[j] = ffma2(dup2(B[j][q].z), xv[4 * q + 2], acc[j]);
          acc[j] = ffma2(dup2(B[j][q].w), xv[4 * q + 3], acc[j]);
        }
    }
  }
}

// ---------------- stage building blocks ----------------

template<int OUT, int CIN, bool NORM>
__device__ __forceinline__ void matvec_v(const float* __restrict__ W,
                                         float (*x)[256][R],
                                         float (*y)[256][R],
                                         float (*nrm)[R],
                                         int g, int p)
{
  constexpr int NP = OUT / G / 4;   // passes of 4 outputs
#pragma unroll
  for (int pass = 0; pass < NP; ++pass) {
    const int oOff = pass * 4 * G;
    u64 acc[4][3];
#pragma unroll
    for (int j = 0; j < 4; ++j) { acc[j][0] = 0ull; acc[j][1] = 0ull; acc[j][2] = 0ull; }
    vdot4<CIN>(W, oOff, x, acc, g, p);
#pragma unroll
    for (int j = 0; j < 4; ++j) {
      const int o = oOff + g + G * j;
      st2(&y[0][o][2 * p], acc[j][0]);
      st2(&y[1][o][2 * p], acc[j][1]);
      st2(&y[2][o][2 * p], acc[j][2]);
      if (NORM) {
        u64 s = fmul2(acc[j][0], acc[j][0]);
        s = ffma2(acc[j][1], acc[j][1], s);
        s = ffma2(acc[j][2], acc[j][2], s);
        F2 t; t.u = s;
        F2 n; n.f.x = sqrtf(t.f.x); n.f.y = sqrtf(t.f.y);
        st2(&nrm[o][2 * p], n.u);
      }
    }
  }
}

template<int OUT, int K1, int K2>
__device__ __forceinline__ void matvec_s2(const float* __restrict__ W,
                                          float (*x1)[R], float (*x2)[R],
                                          float (*y)[R], int g, int p)
{
  constexpr int J = OUT / G;
  u64 acc[J];
#pragma unroll
  for (int j = 0; j < J; ++j) acc[j] = 0ull;
  sdot_seg<J, K1 + K2, 0,  K1>(W, x1, acc, g, p);
  sdot_seg<J, K1 + K2, K1, K2>(W, x2, acc, g, p);
#pragma unroll
  for (int j = 0; j < J; ++j) st2(&y[g + G * j][2 * p], acc[j]);
}

template<int OUT, int H, int KG>
__device__ __forceinline__ void gated_outv(const float* __restrict__ Wvo,
                                           const float* __restrict__ Wg,
                                           const float* __restrict__ bg,
                                           float (*vh)[256][R],
                                           float (*so)[R],
                                           float (*v)[256][R],
                                           int g, int p)
{
  constexpr int J = OUT / G;
  u64 gacc[J];
#pragma unroll
  for (int j = 0; j < J; ++j) gacc[j] = 0ull;
  sdot_seg<J, KG, 0, KG>(Wg, so, gacc, g, p);
  u64 gate[J];
#pragma unroll
  for (int j = 0; j < J; ++j) {
    const float b = __ldg(&bg[g + G * j]);
    F2 t; t.u = gacc[j];
    F2 gt;
    gt.f.x = 1.f / (1.f + __expf(-(t.f.x + b)));
    gt.f.y = 1.f / (1.f + __expf(-(t.f.y + b)));
    gate[j] = gt.u;
  }
  constexpr int NP = J / 4;
#pragma unroll
  for (int pass = 0; pass < NP; ++pass) {
    const int oOff = pass * 4 * G;
    u64 acc[4][3];
#pragma unroll
    for (int j = 0; j < 4; ++j) { acc[j][0] = 0ull; acc[j][1] = 0ull; acc[j][2] = 0ull; }
    vdot4<H>(Wvo, oOff, vh, acc, g, p);
#pragma unroll
    for (int j = 0; j < 4; ++j) {
      const int o = oOff + g + G * j;
      const u64 gt = gate[j + 4 * pass];
      st2(&v[0][o][2 * p], fmul2(gt, acc[j][0]));
      st2(&v[1][o][2 * p], fmul2(gt, acc[j][1]));
      st2(&v[2][o][2 * p], fmul2(gt, acc[j][2]));
    }
  }
}

template<int OUT, bool LEAKY>
__device__ __forceinline__ void scalar_act(float (*so)[R], float (*dst)[R], int g, int p)
{
  constexpr int J = OUT / G;
#pragma unroll
  for (int j = 0; j < J; ++j) {
    const int o = g + G * j;
    F2 t; t.u = ld2(&so[o][2 * p]);
    if (LEAKY) {
      t.f.x = t.f.x >= 0.f ? t.f.x : 0.01f * t.f.x;
      t.f.y = t.f.y >= 0.f ? t.f.y : 0.01f * t.f.y;
    }
    st2(&dst[o][2 * p], t.u);
  }
}

template<int OUT>
__device__ __forceinline__ void vnleaky_ew(float (*x)[256][R], float (*d)[256][R], int g, int p)
{
  constexpr int J = OUT / G;
#pragma unroll
  for (int j = 0; j < J; ++j) {
    const int o = g + G * j;
    F2 x0, x1, x2, d0, d1, d2;
    x0.u = ld2(&x[0][o][2 * p]); x1.u = ld2(&x[1][o][2 * p]); x2.u = ld2(&x[2][o][2 * p]);
    d0.u = ld2(&d[0][o][2 * p]); d1.u = ld2(&d[1][o][2 * p]); d2.u = ld2(&d[2][o][2 * p]);
    u64 dotu = fmul2(x0.u, d0.u); dotu = ffma2(x1.u, d1.u, dotu); dotu = ffma2(x2.u, d2.u, dotu);
    u64 dsqu = fmul2(d0.u, d0.u); dsqu = ffma2(d1.u, d1.u, dsqu); dsqu = ffma2(d2.u, d2.u, dsqu);
    F2 dot, dsq; dot.u = dotu; dsq.u = dsqu;
    F2 o0, o1, o2;
#pragma unroll
    for (int h = 0; h < 2; ++h) {
      const float dt = h ? dot.f.y : dot.f.x;
      const float ds = h ? dsq.f.y : dsq.f.x;
      const float xa = h ? x0.f.y : x0.f.x;
      const float xb = h ? x1.f.y : x1.f.x;
      const float xc = h ? x2.f.y : x2.f.x;
      const float da = h ? d0.f.y : d0.f.x;
      const float db = h ? d1.f.y : d1.f.x;
      const float dc = h ? d2.f.y : d2.f.x;
      const float t = dt / (ds + 1e-6f);
      const bool pos = (dt >= 0.f);
      const float na = pos ? xa : (xa - t * da);
      const float nb = pos ? xb : (xb - t * db);
      const float nc = pos ? xc : (xc - t * dc);
      const float ra = 0.2f * xa + 0.8f * na;
      const float rb = 0.2f * xb + 0.8f * nb;
      const float rc = 0.2f * xc + 0.8f * nc;
      if (h) { o0.f.y = ra; o1.f.y = rb; o2.f.y = rc; }
      else   { o0.f.x = ra; o1.f.x = rb; o2.f.x = rc; }
    }
    st2(&x[0][o][2 * p], o0.u);
    st2(&x[1][o][2 * p], o1.u);
    st2(&x[2][o][2 * p], o2.u);
  }
}

__global__ __launch_bounds__(NT, 1)
void pe_kernel(const float* __restrict__ h_sca, const float* __restrict__ h_vec,
               const float* __restrict__ pos_compose, const float* __restrict__ pos,
               const float* __restrict__ g1_Wvh, const float* __restrict__ g1_Ws,
               const float* __restrict__ g1_Wvo, const float* __restrict__ g1_Wg,
               const float* __restrict__ g1_bg,  const float* __restrict__ g1_Wd,
               const float* __restrict__ g2_Wvh, const float* __restrict__ g2_Ws,
               const float* __restrict__ g2_Wvo, const float* __restrict__ g2_Wg,
               const float* __restrict__ g2_bg,
               const float* __restrict__ a1_Wvh, const float* __restrict__ a1_Ws,
               const float* __restrict__ a1_Wvo, const float* __restrict__ a1_Wg,
               const float* __restrict__ a1_bg,  const float* __restrict__ a1_Wd,
               const float* __restrict__ a2_Wvh, const float* __restrict__ a2_Ws,
               const float* __restrict__ a2_Wvo, const float* __restrict__ a2_Wg,
               const float* __restrict__ a2_bg,  const float* __restrict__ a2_Wd,
               const float* __restrict__ f_Wvh,  const float* __restrict__ f_Ws,
               const int* __restrict__ idx_focal,
               float* __restrict__ out, int F)
{
  extern __shared__ char smraw[];
  SM& S = *reinterpret_cast<SM*>(smraw);
  const int tid = threadIdx.x;
  const int g = tid >> 3;    // channel group 0..31
  const int p = tid & 7;     // row pair     0..7
  const int row0 = blockIdx.x * R;

  if (tid < R) {
    const int row = row0 + tid;
    S.nidx[tid] = (row < F) ? idx_focal[row] : 0;
  }
  __syncthreads();

  if (tid < 3 * R) {
    const int rr = tid / 3, i = tid % 3;
    const int row = row0 + rr;
    const int n = S.nidx[rr];
    const float pv = (row < F) ? pos[(size_t)row * 3 + i] : 0.f;
    S.rp[i][rr] = pv - pos_compose[(size_t)n * 3 + i];
  }

  for (int rr = 0; rr < R; ++rr) {
    const size_t n = (size_t)S.nidx[rr];
    S.ssc[tid][rr] = __ldg(&h_sca[n * 256 + tid]);
    if (tid < 192) S.sv[tid % 3][tid / 3][rr] = __ldg(&h_vec[n * 192 + tid]);
  }
  __syncthreads();

  // ================= g1: gv_perceptron =================
  matvec_v<128, 64, true>(g1_Wvh, S.sv, S.sh, S.snorm, g, p);
  __syncthreads();
  matvec_s2<128, 128, 256>(g1_Ws, S.snorm, S.ssc, S.so, g, p);
  __syncthreads();
  gated_outv<128, 128, 128>(g1_Wvo, g1_Wg, g1_bg, S.sh, S.so, S.sv, g, p);
  scalar_act<128, true>(S.so, S.ssc, g, p);
  __syncthreads();
  matvec_v<128, 128, false>(g1_Wd, S.sv, S.sh, S.snorm, g, p);
  __syncthreads();
  vnleaky_ew<128>(S.sv, S.sh, g, p);
  __syncthreads();

  // ================= g2: gv_linear =================
  matvec_v<128, 128, true>(g2_Wvh, S.sv, S.sh, S.snorm, g, p);
  __syncthreads();
  matvec_s2<128, 128, 128>(g2_Ws, S.snorm, S.ssc, S.so, g, p);
  __syncthreads();
  gated_outv<128, 128, 128>(g2_Wvo, g2_Wg, g2_bg, S.sh, S.so, S.sv, g, p);
  scalar_act<128, false>(S.so, S.ssc, g, p);
  __syncthreads();

  // ================= a1: gv_perceptron =================
  matvec_v<256, 128, true>(a1_Wvh, S.sv, S.sh, S.snorm, g, p);
  __syncthreads();
  matvec_s2<128, 256, 128>(a1_Ws, S.snorm, S.ssc, S.so, g, p);
  __syncthreads();
  gated_outv<256, 256, 128>(a1_Wvo, a1_Wg, a1_bg, S.sh, S.so, S.sv, g, p);
  scalar_act<128, true>(S.so, S.ssc, g, p);
  __syncthreads();
  matvec_v<256, 256, false>(a1_Wd, S.sv, S.sh, S.snorm, g, p);
  __syncthreads();
  vnleaky_ew<256>(S.sv, S.sh, g, p);
  __syncthreads();

  // ===== split: inner = <x_vec2, relpos> -> ssc[128..255] =====
  {
    const u64 rp0 = ld2(&S.rp[0][2 * p]);
    const u64 rp1 = ld2(&S.rp[1][2 * p]);
    const u64 rp2 = ld2(&S.rp[2][2 * p]);
#pragma unroll
    for (int j = 0; j < 4; ++j) {
      const int o = g + G * j;
      u64 acc = fmul2(ld2(&S.sv[0][128 + o][2 * p]), rp0);
      acc = ffma2(ld2(&S.sv[1][128 + o][2 * p]), rp1, acc);
      acc = ffma2(ld2(&S.sv[2][128 + o][2 * p]), rp2, acc);
      st2(&S.ssc[128 + o][2 * p], acc);
    }
  }
  __syncthreads();

  // ================= a2: gv_perceptron =================
  matvec_v<128, 128, true>(a2_Wvh, S.sv, S.sh, S.snorm, g, p);
  __syncthreads();
  matvec_s2<128, 128, 256>(a2_Ws, S.snorm, S.ssc, S.so, g, p);
  __syncthreads();
  gated_outv<128, 128, 128>(a2_Wvo, a2_Wg, a2_bg, S.sh, S.so, S.sv, g, p);
  scalar_act<128, true>(S.so, S.ssc, g, p);
  __syncthreads();
  matvec_v<128, 128, false>(a2_Wd, S.sv, S.sh, S.snorm, g, p);
  __syncthreads();
  vnleaky_ew<128>(S.sv, S.sh, g, p);
  __syncthreads();

  // ================= final =================
  matvec_v<128, 128, true>(f_Wvh, S.sv, S.sh, S.snorm, g, p);
  __syncthreads();
  {
    u64 acc = 0ull;
#pragma unroll
    for (int kk = 0; kk < 8; ++kk) {
      const int k = g * 8 + kk;
      const u64 xv = (k < 128) ? ld2(&S.snorm[k][2 * p]) : ld2(&S.ssc[k - 128][2 * p]);
      acc = ffma2(dup2(__ldg(&f_Ws[k])), xv, acc);
    }
    st2(&S.so[g][2 * p], acc);
  }
  __syncthreads();
  if (tid < R) {
    const int row = row0 + tid;
    float acc = 0.f;
#pragma unroll
    for (int gg = 0; gg < G; ++gg) acc += S.so[gg][tid];
    if (row < F) out[row] = acc;
  }
}

extern "C" void kernel_launch(void* const* d_in, const int* in_sizes, int n_in,
                              void* d_out, int out_size)
{
  const float* h_sca       = (const float*)d_in[0];
  const float* h_vec       = (const float*)d_in[1];
  const float* pos_compose = (const float*)d_in[2];
  const float* pos         = (const float*)d_in[3];
  const float* g1_Wvh = (const float*)d_in[4];
  const float* g1_Ws  = (const float*)d_in[5];
  const float* g1_Wvo = (const float*)d_in[6];
  const float* g1_Wg  = (const float*)d_in[7];
  const float* g1_bg  = (const float*)d_in[8];
  const float* g1_Wd  = (const float*)d_in[9];
  const float* g2_Wvh = (const float*)d_in[10];
  const float* g2_Ws  = (const float*)d_in[11];
  const float* g2_Wvo = (const float*)d_in[12];
  const float* g2_Wg  = (const float*)d_in[13];
  const float* g2_bg  = (const float*)d_in[14];
  const float* a1_Wvh = (const float*)d_in[15];
  const float* a1_Ws  = (const float*)d_in[16];
  const float* a1_Wvo = (const float*)d_in[17];
  const float* a1_Wg  = (const float*)d_in[18];
  const float* a1_bg  = (const float*)d_in[19];
  const float* a1_Wd  = (const float*)d_in[20];
  const float* a2_Wvh = (const float*)d_in[21];
  const float* a2_Ws  = (const float*)d_in[22];
  const float* a2_Wvo = (const float*)d_in[23];
  const float* a2_Wg  = (const float*)d_in[24];
  const float* a2_bg  = (const float*)d_in[25];
  const float* a2_Wd  = (const float*)d_in[26];
  const float* f_Wvh  = (const float*)d_in[27];
  const float* f_Ws   = (const float*)d_in[28];
  const int*   idx_focal = (const int*)d_in[29];

  const int F = in_sizes[3] / 3;   // pos is (F, 3)
  const int grid = (F + R - 1) / R;

  cudaFuncSetAttribute(pe_kernel, cudaFuncAttributeMaxDynamicSharedMemorySize,
                       (int)sizeof(SM));

  pe_kernel<<<grid, NT, sizeof(SM)>>>(
      h_sca, h_vec, pos_compose, pos,
      g1_Wvh, g1_Ws, g1_Wvo, g1_Wg, g1_bg, g1_Wd,
      g2_Wvh, g2_Ws, g2_Wvo, g2_Wg, g2_bg,
      a1_Wvh, a1_Ws, a1_Wvo, a1_Wg, a1_bg, a1_Wd,
      a2_Wvh, a2_Ws, a2_Wvo, a2_Wg, a2_bg, a2_Wd,
      f_Wvh, f_Ws, idx_focal,
      (float*)d_out, F);
}